// round 13
// baseline (speedup 1.0000x reference)
#include <cuda_runtime.h>
#include <cuda_fp16.h>
#include <cstdint>
#include <math.h>

#define SEQ 2048
#define EMB 1024
#define NBQ 256
#define NH 16
#define HD 64
#define NBATCH 2
#define NROWS (NBATCH*SEQ)   // 4096
#define NKT (SEQ/64)         // 32 kv tiles
#define NQT (SEQ/128)        // 16 q tiles

// ---------------- scratch (device globals) ---------------------------------
__device__ __half g_Wq[EMB*EMB];     // transposed [out][in]
__device__ __half g_Wk[EMB*EMB];
__device__ __half g_Wv[EMB*EMB];
__device__ __half g_Wo[EMB*EMB];
__device__ __half g_xr[NROWS*EMB];   // fp16 input
__device__ __half g_Q[NROWS*EMB];    // prescaled by 1/8
__device__ __half g_K[NROWS*EMB];
__device__ __half g_V[NROWS*EMB];    // [b,s,h,d]
__device__ __half g_Vt[NROWS*EMB];   // [b,h,d,s]
__device__ __half g_ctx[NROWS*EMB];
__device__ int    g_msum[NQT*NKT];

// ---------------- helpers ---------------------------------------------------
__device__ __forceinline__ uint32_t h2u(__half2 h) {
    return *reinterpret_cast<uint32_t*>(&h);
}

__device__ __forceinline__ void mma_f16(float* d, const unsigned* a, const unsigned* b) {
    asm volatile(
        "mma.sync.aligned.m16n8k16.row.col.f32.f16.f16.f32 "
        "{%0,%1,%2,%3},{%4,%5,%6,%7},{%8,%9},{%0,%1,%2,%3};"
        : "+f"(d[0]), "+f"(d[1]), "+f"(d[2]), "+f"(d[3])
        : "r"(a[0]), "r"(a[1]), "r"(a[2]), "r"(a[3]), "r"(b[0]), "r"(b[1]));
}

#define LDSM4(r0, r1, r2, r3, addr)                                            \
    asm volatile("ldmatrix.sync.aligned.m8n8.x4.shared.b16 {%0,%1,%2,%3}, [%4];" \
                 : "=r"(r0), "=r"(r1), "=r"(r2), "=r"(r3) : "r"(addr))

__device__ __forceinline__ uint32_t sa(const void* p) {
    return (uint32_t)__cvta_generic_to_shared(p);
}
__device__ __forceinline__ void cpa16(uint32_t s, const void* g) {
    asm volatile("cp.async.cg.shared.global [%0], [%1], 16;" :: "r"(s), "l"(g));
}
__device__ __forceinline__ void cp_commit() {
    asm volatile("cp.async.commit_group;" ::: "memory");
}
__device__ __forceinline__ void cp_wait0() {
    asm volatile("cp.async.wait_group 0;" ::: "memory");
}

// ---------------- x -> fp16 --------------------------------------------------
__global__ void round_kernel(const float* __restrict__ in, __half* __restrict__ outp, int n4) {
    int i = blockIdx.x * blockDim.x + threadIdx.x;
    if (i >= n4) return;
    float4 v = ((const float4*)in)[i];
    __half2* o = (__half2*)(outp + i * 4);
    o[0] = __floats2half2_rn(v.x, v.y);
    o[1] = __floats2half2_rn(v.z, v.w);
}

// ---------------- weight expansion: transposed [out][in], fp16 --------------
struct Exp4 { const float* W[4]; __half* Wb[4]; };

__global__ void expand4_kernel(Exp4 e) {
    int z = blockIdx.y;
    int idx = blockIdx.x * blockDim.x + threadIdx.x;
    if (idx >= NBQ * NBQ) return;
    int o = idx / NBQ;
    int n = idx % NBQ;
    const float* w = e.W[z] + (o * NBQ + n) * 4;
    float w0 = w[0], w1 = w[1], w2 = w[2], w3 = w[3];
    float M[4][4] = {{ w0,  w1,  w2,  w3},
                     {-w1,  w0,  w3, -w2},
                     {-w2, -w3,  w0,  w1},
                     {-w3,  w2, -w1,  w0}};
    __half* Wb = e.Wb[z];
#pragma unroll
    for (int k = 0; k < 4; k++) {
        __half2* row = (__half2*)(Wb + (long)(o * 4 + k) * EMB + n * 4);
        row[0] = __floats2half2_rn(M[0][k], M[1][k]);
        row[1] = __floats2half2_rn(M[2][k], M[3][k]);
    }
}

// ---------------- mask tile summary (128q x 64k tiles) ----------------------
__global__ void mask_summary(const int* __restrict__ mask, int* __restrict__ sum) {
    int tile = blockIdx.x;
    int qt = tile / NKT, kt = tile % NKT;
    int tid = threadIdx.x;
    int ok = 1;
    for (int i = tid; i < 128*64; i += 256) {
        int r = i / 64, c = i % 64;
        ok &= (mask[(qt*128 + r) * SEQ + kt*64 + c] != 0);
    }
    int allok = __syncthreads_and(ok);
    if (tid == 0) sum[tile] = allok;
}

// ---------------- V transpose: [b,s,h,d] -> [b,h,d,s], fp16 -----------------
__global__ __launch_bounds__(256) void vtrans_kernel(
    const __half* __restrict__ V, __half* __restrict__ Vt)
{
    __shared__ __half Ts[64][72];
    int bh = blockIdx.y;
    int b = bh / NH, h = bh % NH;
    int st = blockIdx.x * 64;
    int tid = threadIdx.x;
    int s = tid >> 2;
    int d0 = (tid & 3) * 16;
    const __half* src = V + (long)(b * SEQ + st + s) * EMB + h * HD + d0;
#pragma unroll
    for (int c = 0; c < 16; c++) Ts[d0 + c][s] = src[c];
    __syncthreads();
    int d = tid >> 2;
    int s0 = (tid & 3) * 16;
    __half* dst = Vt + ((long)bh * HD + d) * SEQ + st + s0;
#pragma unroll
    for (int c = 0; c < 2; c++)
        *(uint4*)(dst + c * 8) = *(const uint4*)&Ts[d][s0 + c * 8];
}

// ---------------- FP16 GEMM (cp.async + ldmatrix, BK=64) --------------------
// A: [M][K] half.  W: transposed [N][K] half.
#define ASTR 72   // halves; 144B rows -> ldmatrix conflict-free
#define BSTR 72

struct GemmArgs {
    const __half* A;
    const __half* W[3];
    const float* bias[3];
    void* out[3];
    float oscale[3];
    int   half_out;
};

__global__ __launch_bounds__(256, 2) void gemm_f16(GemmArgs ga) {
    extern __shared__ __half gsm[];
    __half* Asm = gsm;                       // 2 * 128*ASTR
    __half* Bsm = gsm + 2 * 128 * ASTR;      // 2 * 128*BSTR

    int tid = threadIdx.x;
    int z = blockIdx.z;
    const __half* A = ga.A;
    const __half* W = ga.W[z];
    const float* bias = ga.bias[z];

    int bm = blockIdx.y * 128;
    int bn = blockIdx.x * 128;
    int warp = tid / 32, lane = tid % 32;
    int gid = lane >> 2, tig = lane & 3;
    int wm = (warp / 4) * 64, wn = (warp % 4) * 32;
    int lrow = lane & 7, lmat = lane >> 3;

    int r128 = tid >> 1;           // 0..127
    int ch   = (tid & 1) * 32;     // 32-half chunk (64B)

    float acc[4][4][4];
#pragma unroll
    for (int mt = 0; mt < 4; mt++)
#pragma unroll
        for (int nt = 0; nt < 4; nt++)
#pragma unroll
            for (int r = 0; r < 4; r++) acc[mt][nt][r] = 0.0f;

#define GLOAD(kt, buf)                                                         \
    {                                                                          \
        const __half* asrc = A + (long)(bm + r128) * EMB + (kt) * 64 + ch;     \
        uint32_t adst = sa(Asm + (buf) * 128 * ASTR + r128 * ASTR + ch);       \
        _Pragma("unroll")                                                      \
        for (int j = 0; j < 4; j++) cpa16(adst + j * 16, asrc + j * 8);        \
        const __half* bsrc = W + (long)(bn + r128) * EMB + (kt) * 64 + ch;     \
        uint32_t bdst = sa(Bsm + (buf) * 128 * BSTR + r128 * BSTR + ch);       \
        _Pragma("unroll")                                                      \
        for (int j = 0; j < 4; j++) cpa16(bdst + j * 16, bsrc + j * 8);        \
    }

    GLOAD(0, 0);
    cp_commit();
    cp_wait0();
    __syncthreads();

    for (int kt = 0; kt < EMB / 64; kt++) {
        if (kt + 1 < EMB / 64) {
            GLOAD(kt + 1, (kt + 1) & 1);
            cp_commit();
        }

        const __half* As = Asm + (kt & 1) * 128 * ASTR;
        const __half* Bs = Bsm + (kt & 1) * 128 * BSTR;
#pragma unroll
        for (int ks = 0; ks < 4; ks++) {
            int k0 = ks * 16;
            unsigned af[4][4], bf[4][2];
#pragma unroll
            for (int mt = 0; mt < 4; mt++) {
                uint32_t addr = sa(As + (wm + mt * 16 + ((lmat & 1) << 3) + lrow) * ASTR
                                   + k0 + ((lmat >> 1) << 3));
                LDSM4(af[mt][0], af[mt][1], af[mt][2], af[mt][3], addr);
            }
#pragma unroll
            for (int p = 0; p < 2; p++) {
                uint32_t addr = sa(Bs + (wn + p * 16 + ((lmat >> 1) << 3) + lrow) * BSTR
                                   + k0 + ((lmat & 1) << 3));
                LDSM4(bf[2*p][0], bf[2*p][1], bf[2*p+1][0], bf[2*p+1][1], addr);
            }
#pragma unroll
            for (int mt = 0; mt < 4; mt++)
#pragma unroll
                for (int nt = 0; nt < 4; nt++)
                    mma_f16(acc[mt][nt], af[mt], bf[nt]);
        }
        if (kt + 1 < EMB / 64) {
            cp_wait0();
            __syncthreads();
        }
    }

    float os = ga.oscale[z];
#pragma unroll
    for (int mt = 0; mt < 4; mt++)
#pragma unroll
        for (int nt = 0; nt < 4; nt++) {
            int gm = bm + wm + mt * 16 + gid;
            int gn = bn + wn + nt * 8 + tig * 2;
            float b0 = bias[gn], b1 = bias[gn + 1];
            float v0 = (acc[mt][nt][0] + b0) * os;
            float v1 = (acc[mt][nt][1] + b1) * os;
            float v2 = (acc[mt][nt][2] + b0) * os;
            float v3 = (acc[mt][nt][3] + b1) * os;
            if (ga.half_out) {
                __half* C = (__half*)ga.out[z];
                *(__half2*)(C + (long)gm * EMB + gn) = __floats2half2_rn(v0, v1);
                *(__half2*)(C + (long)(gm + 8) * EMB + gn) = __floats2half2_rn(v2, v3);
            } else {
                float* C = (float*)ga.out[z];
                *(float2*)(C + (long)gm * EMB + gn) = make_float2(v0, v1);
                *(float2*)(C + (long)(gm + 8) * EMB + gn) = make_float2(v2, v3);
            }
        }
}

// ---------------- FP16 flash attention (unchanged from R10) -----------------
#define BQ 128
#define BKV 64
#define QSTR 72
#define KSTR 72
#define VSTR 72

__global__ __launch_bounds__(256, 2) void flash_f16(
    const __half* __restrict__ Q, const __half* __restrict__ K,
    const __half* __restrict__ Vt, const int* __restrict__ mask,
    const int* __restrict__ msum, __half* __restrict__ ctx)
{
    extern __shared__ __half fsm[];
    __half* Qs = fsm;
    __half* Ks = Qs + BQ * QSTR;
    __half* Vs = Ks + 2 * BKV * KSTR;

    int tid = threadIdx.x;
    int w = tid / 32, lane = tid % 32;
    int gid = lane >> 2, tig = lane & 3;
    int lrow = lane & 7, lmat = lane >> 3;
    int qt = blockIdx.x, h = blockIdx.y, b = blockIdx.z;
    int q0 = qt * BQ;
    int bh = b * NH + h;

    {
        int row = tid >> 1;
        int c0 = (tid & 1) * 32;
        const __half* g = Q + (long)(b * SEQ + q0 + row) * EMB + h * HD + c0;
        uint32_t s = sa(Qs + row * QSTR + c0);
#pragma unroll
        for (int j = 0; j < 4; j++) cpa16(s + j * 16, g + j * 8);
    }
    {
        int row = tid >> 2;
        int c0 = (tid & 3) * 16;
        const __half* kg = K + (long)(b * SEQ + row) * EMB + h * HD + c0;
        uint32_t ksm = sa(Ks + row * KSTR + c0);
        cpa16(ksm, kg); cpa16(ksm + 16, kg + 8);
        const __half* vg = Vt + ((long)bh * HD + row) * SEQ + c0;
        uint32_t vsm = sa(Vs + row * VSTR + c0);
        cpa16(vsm, vg); cpa16(vsm + 16, vg + 8);
    }
    cp_commit();
    cp_wait0();
    __syncthreads();

    unsigned aq[4][4];
#pragma unroll
    for (int ks = 0; ks < 4; ks++) {
        uint32_t addr = sa(Qs + (w * 16 + ((lmat & 1) << 3) + lrow) * QSTR
                           + ks * 16 + ((lmat >> 1) << 3));
        LDSM4(aq[ks][0], aq[ks][1], aq[ks][2], aq[ks][3], addr);
    }

    float o[8][4];
#pragma unroll
    for (int dt = 0; dt < 8; dt++)
#pragma unroll
        for (int r = 0; r < 4; r++) o[dt][r] = 0.0f;
    float mA = -1e30f, mB = -1e30f, lA = 0.0f, lB = 0.0f;

    for (int kt = 0; kt < NKT; kt++) {
        if (kt + 1 < NKT) {
            int nb = (kt + 1) & 1;
            int row = tid >> 2;
            int c0 = (tid & 3) * 16;
            const __half* kg = K + (long)(b * SEQ + (kt + 1) * BKV + row) * EMB + h * HD + c0;
            uint32_t ksm = sa(Ks + nb * BKV * KSTR + row * KSTR + c0);
            cpa16(ksm, kg); cpa16(ksm + 16, kg + 8);
            const __half* vg = Vt + ((long)bh * HD + row) * SEQ + (kt + 1) * BKV + c0;
            uint32_t vsm = sa(Vs + nb * HD * VSTR + row * VSTR + c0);
            cpa16(vsm, vg); cpa16(vsm + 16, vg + 8);
            cp_commit();
        }

        const __half* Kb = Ks + (kt & 1) * BKV * KSTR;
        const __half* Vb = Vs + (kt & 1) * HD * VSTR;

        float s[8][4];
#pragma unroll
        for (int nt = 0; nt < 8; nt++)
#pragma unroll
            for (int r = 0; r < 4; r++) s[nt][r] = 0.0f;
#pragma unroll
        for (int ks = 0; ks < 4; ks++) {
            int k0 = ks * 16;
            unsigned bk[8][2];
#pragma unroll
            for (int p = 0; p < 4; p++) {
                uint32_t addr = sa(Kb + (p * 16 + ((lmat >> 1) << 3) + lrow) * KSTR
                                   + k0 + ((lmat & 1) << 3));
                LDSM4(bk[2*p][0], bk[2*p][1], bk[2*p+1][0], bk[2*p+1][1], addr);
            }
#pragma unroll
            for (int nt = 0; nt < 8; nt++)
                mma_f16(s[nt], aq[ks], bk[nt]);
        }

        if (!msum[qt * NKT + kt]) {
            int qrA = q0 + w * 16 + gid;
            int qrB = qrA + 8;
#pragma unroll
            for (int nt = 0; nt < 8; nt++) {
                int kc = kt * 64 + nt * 8 + tig * 2;
                const int* mpA = mask + (long)qrA * SEQ + kc;
                const int* mpB = mask + (long)qrB * SEQ + kc;
                if (mpA[0] == 0) s[nt][0] = -1e30f;
                if (mpA[1] == 0) s[nt][1] = -1e30f;
                if (mpB[0] == 0) s[nt][2] = -1e30f;
                if (mpB[1] == 0) s[nt][3] = -1e30f;
            }
        }

        float mxA = -1e30f, mxB = -1e30f;
#pragma unroll
        for (int nt = 0; nt < 8; nt++) {
            mxA = fmaxf(mxA, fmaxf(s[nt][0], s[nt][1]));
            mxB = fmaxf(mxB, fmaxf(s[nt][2], s[nt][3]));
        }
#pragma unroll
        for (int off = 1; off < 4; off <<= 1) {
            mxA = fmaxf(mxA, __shfl_xor_sync(0xffffffffu, mxA, off));
            mxB = fmaxf(mxB, __shfl_xor_sync(0xffffffffu, mxB, off));
        }
        float mnA = fmaxf(mA, mxA), mnB = fmaxf(mB, mxB);
        float fA = __expf(mA - mnA), fB = __expf(mB - mnB);
        mA = mnA; mB = mnB;
        float sumA = 0.0f, sumB = 0.0f;
#pragma unroll
        for (int nt = 0; nt < 8; nt++) {
            s[nt][0] = __expf(s[nt][0] - mA);
            s[nt][1] = __expf(s[nt][1] - mA);
            s[nt][2] = __expf(s[nt][2] - mB);
            s[nt][3] = __expf(s[nt][3] - mB);
            sumA += s[nt][0] + s[nt][1];
            sumB += s[nt][2] + s[nt][3];
        }
#pragma unroll
        for (int off = 1; off < 4; off <<= 1) {
            sumA += __shfl_xor_sync(0xffffffffu, sumA, off);
            sumB += __shfl_xor_sync(0xffffffffu, sumB, off);
        }
        lA = lA * fA + sumA;
        lB = lB * fB + sumB;
#pragma unroll
        for (int dt = 0; dt < 8; dt++) {
            o[dt][0] *= fA; o[dt][1] *= fA;
            o[dt][2] *= fB; o[dt][3] *= fB;
        }

#pragma unroll
        for (int ks = 0; ks < 4; ks++) {
            unsigned pa[4];
            pa[0] = h2u(__floats2half2_rn(s[2*ks][0],   s[2*ks][1]));
            pa[1] = h2u(__floats2half2_rn(s[2*ks][2],   s[2*ks][3]));
            pa[2] = h2u(__floats2half2_rn(s[2*ks+1][0], s[2*ks+1][1]));
            pa[3] = h2u(__floats2half2_rn(s[2*ks+1][2], s[2*ks+1][3]));
            int k0 = ks * 16;
            unsigned bv[8][2];
#pragma unroll
            for (int p = 0; p < 4; p++) {
                uint32_t addr = sa(Vb + (p * 16 + ((lmat >> 1) << 3) + lrow) * VSTR
                                   + k0 + ((lmat & 1) << 3));
                LDSM4(bv[2*p][0], bv[2*p][1], bv[2*p+1][0], bv[2*p+1][1], addr);
            }
#pragma unroll
            for (int dt = 0; dt < 8; dt++)
                mma_f16(o[dt], pa, bv[dt]);
        }

        if (kt + 1 < NKT) {
            cp_wait0();
            __syncthreads();
        }
    }

    float invA = 1.0f / lA, invB = 1.0f / lB;
    long rowA = (long)(b * SEQ + q0 + w * 16 + gid) * EMB;
    long rowB = rowA + 8L * EMB;
#pragma unroll
    for (int dt = 0; dt < 8; dt++) {
        int gn = h * HD + dt * 8 + tig * 2;
        *(__half2*)(ctx + rowA + gn) = __floats2half2_rn(o[dt][0] * invA, o[dt][1] * invA);
        *(__half2*)(ctx + rowB + gn) = __floats2half2_rn(o[dt][2] * invB, o[dt][3] * invB);
    }
}

// ---------------- launch ----------------------------------------------------
extern "C" void kernel_launch(void* const* d_in, const int* in_sizes, int n_in,
                              void* d_out, int out_size)
{
    const float* x    = (const float*)d_in[0];
    const int*   mask = (const int*)  d_in[1];
    const float* Wq   = (const float*)d_in[2];
    const float* bq   = (const float*)d_in[3];
    const float* Wk   = (const float*)d_in[4];
    const float* bk   = (const float*)d_in[5];
    const float* Wv   = (const float*)d_in[6];
    const float* bv   = (const float*)d_in[7];
    const float* Wo   = (const float*)d_in[8];
    const float* bo   = (const float*)d_in[9];
    float* out = (float*)d_out;

    __half *pWq, *pWk, *pWv, *pWo, *pXr, *pQ, *pK, *pV, *pVt, *pCtx;
    int* pMsum;
    cudaGetSymbolAddress((void**)&pWq, g_Wq);
    cudaGetSymbolAddress((void**)&pWk, g_Wk);
    cudaGetSymbolAddress((void**)&pWv, g_Wv);
    cudaGetSymbolAddress((void**)&pWo, g_Wo);
    cudaGetSymbolAddress((void**)&pXr, g_xr);
    cudaGetSymbolAddress((void**)&pQ,  g_Q);
    cudaGetSymbolAddress((void**)&pK,  g_K);
    cudaGetSymbolAddress((void**)&pV,  g_V);
    cudaGetSymbolAddress((void**)&pVt, g_Vt);
    cudaGetSymbolAddress((void**)&pCtx, g_ctx);
    cudaGetSymbolAddress((void**)&pMsum, g_msum);

    const int gemm_smem  = (2*128*ASTR + 2*128*BSTR) * (int)sizeof(__half);          // 72KB
    const int flash_smem = (BQ*QSTR + 2*BKV*KSTR + 2*HD*VSTR) * (int)sizeof(__half); // ~54KB
    cudaFuncSetAttribute(gemm_f16, cudaFuncAttributeMaxDynamicSharedMemorySize, gemm_smem);
    cudaFuncSetAttribute(flash_f16, cudaFuncAttributeMaxDynamicSharedMemorySize, flash_smem);

    // 1. prolog
    Exp4 e;
    e.W[0] = Wq; e.W[1] = Wk; e.W[2] = Wv; e.W[3] = Wo;
    e.Wb[0] = pWq; e.Wb[1] = pWk; e.Wb[2] = pWv; e.Wb[3] = pWo;
    expand4_kernel<<<dim3(NBQ*NBQ/256, 4), 256>>>(e);
    round_kernel<<<(NROWS*EMB/4 + 255)/256, 256>>>(x, pXr, NROWS*EMB/4);
    mask_summary<<<NQT*NKT, 256>>>(mask, pMsum);

    // 2. fused Q/K/V projections (Q prescaled by 1/8; all fp16 outputs)
    GemmArgs qkv;
    qkv.A = pXr;
    qkv.W[0] = pWq; qkv.W[1] = pWk; qkv.W[2] = pWv;
    qkv.bias[0] = bq; qkv.bias[1] = bk; qkv.bias[2] = bv;
    qkv.out[0] = pQ; qkv.out[1] = pK; qkv.out[2] = pV;
    qkv.oscale[0] = 0.125f; qkv.oscale[1] = 1.0f; qkv.oscale[2] = 1.0f;
    qkv.half_out = 1;
    dim3 ggrid(EMB/128, NROWS/128, 3);
    gemm_f16<<<ggrid, 256, gemm_smem>>>(qkv);

    // 2b. transpose V -> [b,h,d,s]
    vtrans_kernel<<<dim3(SEQ/64, NBATCH*NH), 256>>>(pV, pVt);

    // 3. attention
    dim3 agrid(SEQ/BQ, NH, NBATCH);
    flash_f16<<<agrid, 256, flash_smem>>>(pQ, pK, pVt, mask, pMsum, pCtx);

    // 4. output projection -> d_out (fp32)
    GemmArgs og;
    og.A = pCtx;
    og.W[0] = pWo; og.W[1] = pWo; og.W[2] = pWo;
    og.bias[0] = bo; og.bias[1] = bo; og.bias[2] = bo;
    og.out[0] = out; og.out[1] = out; og.out[2] = out;
    og.oscale[0] = 1.0f; og.oscale[1] = 1.0f; og.oscale[2] = 1.0f;
    og.half_out = 0;
    dim3 ogrid(EMB/128, NROWS/128, 1);
    gemm_f16<<<ogrid, 256, gemm_smem>>>(og);
}

// round 15
// speedup vs baseline: 1.0289x; 1.0289x over previous
#include <cuda_runtime.h>
#include <cuda_fp16.h>
#include <cstdint>
#include <math.h>

#define SEQ 2048
#define EMB 1024
#define NBQ 256
#define NH 16
#define HD 64
#define NBATCH 2
#define NROWS (NBATCH*SEQ)   // 4096
#define NKT (SEQ/64)         // 32 kv tiles
#define NQT (SEQ/128)        // 16 q tiles

// ---------------- scratch (device globals) ---------------------------------
__device__ __half g_Wq[EMB*EMB];     // transposed [out][in]
__device__ __half g_Wk[EMB*EMB];
__device__ __half g_Wv[EMB*EMB];
__device__ __half g_Wo[EMB*EMB];
__device__ __half g_xr[NROWS*EMB];   // fp16 input
__device__ __half g_Q[NROWS*EMB];    // prescaled by 1/8
__device__ __half g_K[NROWS*EMB];
__device__ __half g_V[NROWS*EMB];    // [b,s,h,d]
__device__ __half g_Vt[NROWS*EMB];   // [b,h,d,s]
__device__ __half g_ctx[NROWS*EMB];
__device__ int    g_msum[NQT*NKT];

// ---------------- helpers ---------------------------------------------------
__device__ __forceinline__ uint32_t h2u(__half2 h) {
    return *reinterpret_cast<uint32_t*>(&h);
}

__device__ __forceinline__ void mma_f16(float* d, const unsigned* a, const unsigned* b) {
    asm volatile(
        "mma.sync.aligned.m16n8k16.row.col.f32.f16.f16.f32 "
        "{%0,%1,%2,%3},{%4,%5,%6,%7},{%8,%9},{%0,%1,%2,%3};"
        : "+f"(d[0]), "+f"(d[1]), "+f"(d[2]), "+f"(d[3])
        : "r"(a[0]), "r"(a[1]), "r"(a[2]), "r"(a[3]), "r"(b[0]), "r"(b[1]));
}

#define LDSM4(r0, r1, r2, r3, addr)                                            \
    asm volatile("ldmatrix.sync.aligned.m8n8.x4.shared.b16 {%0,%1,%2,%3}, [%4];" \
                 : "=r"(r0), "=r"(r1), "=r"(r2), "=r"(r3) : "r"(addr))

__device__ __forceinline__ uint32_t sa(const void* p) {
    return (uint32_t)__cvta_generic_to_shared(p);
}
__device__ __forceinline__ void cpa16(uint32_t s, const void* g) {
    asm volatile("cp.async.cg.shared.global [%0], [%1], 16;" :: "r"(s), "l"(g));
}
__device__ __forceinline__ void cp_commit() {
    asm volatile("cp.async.commit_group;" ::: "memory");
}
__device__ __forceinline__ void cp_wait0() {
    asm volatile("cp.async.wait_group 0;" ::: "memory");
}
__device__ __forceinline__ void cp_wait1() {
    asm volatile("cp.async.wait_group 1;" ::: "memory");
}

// ---------------- x -> fp16 --------------------------------------------------
__global__ void round_kernel(const float* __restrict__ in, __half* __restrict__ outp, int n4) {
    int i = blockIdx.x * blockDim.x + threadIdx.x;
    if (i >= n4) return;
    float4 v = ((const float4*)in)[i];
    __half2* o = (__half2*)(outp + i * 4);
    o[0] = __floats2half2_rn(v.x, v.y);
    o[1] = __floats2half2_rn(v.z, v.w);
}

// ---------------- weight expansion: transposed [out][in], fp16 --------------
struct Exp4 { const float* W[4]; __half* Wb[4]; };

__global__ void expand4_kernel(Exp4 e) {
    int z = blockIdx.y;
    int idx = blockIdx.x * blockDim.x + threadIdx.x;
    if (idx >= NBQ * NBQ) return;
    int o = idx / NBQ;
    int n = idx % NBQ;
    const float* w = e.W[z] + (o * NBQ + n) * 4;
    float w0 = w[0], w1 = w[1], w2 = w[2], w3 = w[3];
    float M[4][4] = {{ w0,  w1,  w2,  w3},
                     {-w1,  w0,  w3, -w2},
                     {-w2, -w3,  w0,  w1},
                     {-w3,  w2, -w1,  w0}};
    __half* Wb = e.Wb[z];
#pragma unroll
    for (int k = 0; k < 4; k++) {
        __half2* row = (__half2*)(Wb + (long)(o * 4 + k) * EMB + n * 4);
        row[0] = __floats2half2_rn(M[0][k], M[1][k]);
        row[1] = __floats2half2_rn(M[2][k], M[3][k]);
    }
}

// ---------------- mask tile summary (128q x 64k tiles) ----------------------
__global__ void mask_summary(const int* __restrict__ mask, int* __restrict__ sum) {
    int tile = blockIdx.x;
    int qt = tile / NKT, kt = tile % NKT;
    int tid = threadIdx.x;
    int ok = 1;
    for (int i = tid; i < 128*16; i += 256) {
        int r = i / 16, c = i % 16;
        const int4* mp = (const int4*)(mask + (long)(qt*128 + r) * SEQ + kt*64) + c;
        int4 v = *mp;
        ok &= (v.x != 0) & (v.y != 0) & (v.z != 0) & (v.w != 0);
    }
    int allok = __syncthreads_and(ok);
    if (tid == 0) sum[tile] = allok;
}

// ---------------- V transpose: [b,s,h,d] -> [b,h,d,s], fp16 -----------------
__global__ __launch_bounds__(256) void vtrans_kernel(
    const __half* __restrict__ V, __half* __restrict__ Vt)
{
    __shared__ __half Ts[64][72];
    int bh = blockIdx.y;
    int b = bh / NH, h = bh % NH;
    int st = blockIdx.x * 64;
    int tid = threadIdx.x;
    int s = tid >> 2;
    int d0 = (tid & 3) * 16;
    const __half* src = V + (long)(b * SEQ + st + s) * EMB + h * HD + d0;
#pragma unroll
    for (int c = 0; c < 16; c++) Ts[d0 + c][s] = src[c];
    __syncthreads();
    int d = tid >> 2;
    int s0 = (tid & 3) * 16;
    __half* dst = Vt + ((long)bh * HD + d) * SEQ + st + s0;
#pragma unroll
    for (int c = 0; c < 2; c++)
        *(uint4*)(dst + c * 8) = *(const uint4*)&Ts[d][s0 + c * 8];
}

// ---------------- FP16 GEMM (3-stage cp.async + ldmatrix, BK=32) ------------
// A: [M][K] half.  W: transposed [N][K] half.
#define ASTR 40   // halves; 80B rows -> ldmatrix conflict-free
#define BSTR 40
#define NSTG 3

struct GemmArgs {
    const __half* A;
    const __half* W[3];
    const float* bias[3];
    void* out[3];
    float oscale[3];
    int   half_out;
};

__global__ __launch_bounds__(256, 2) void gemm_f16(GemmArgs ga) {
    extern __shared__ __half gsm[];
    __half* Asm = gsm;                          // NSTG * 128*ASTR
    __half* Bsm = gsm + NSTG * 128 * ASTR;      // NSTG * 128*BSTR

    int tid = threadIdx.x;
    int z = blockIdx.z;
    const __half* A = ga.A;
    const __half* W = ga.W[z];
    const float* bias = ga.bias[z];

    int bm = blockIdx.y * 128;
    int bn = blockIdx.x * 128;
    int warp = tid / 32, lane = tid % 32;
    int gid = lane >> 2, tig = lane & 3;
    int wm = (warp / 4) * 64, wn = (warp % 4) * 32;
    int lrow = lane & 7, lmat = lane >> 3;

    int r128 = tid >> 1;           // 0..127
    int ch   = (tid & 1) * 16;     // 16-half chunk (32B)

    float acc[4][4][4];
#pragma unroll
    for (int mt = 0; mt < 4; mt++)
#pragma unroll
        for (int nt = 0; nt < 4; nt++)
#pragma unroll
            for (int r = 0; r < 4; r++) acc[mt][nt][r] = 0.0f;

#define GLOAD(kt, buf)                                                         \
    {                                                                          \
        const __half* asrc = A + (long)(bm + r128) * EMB + (kt) * 32 + ch;     \
        uint32_t adst = sa(Asm + (buf) * 128 * ASTR + r128 * ASTR + ch);       \
        cpa16(adst, asrc); cpa16(adst + 16, asrc + 8);                         \
        const __half* bsrc = W + (long)(bn + r128) * EMB + (kt) * 32 + ch;     \
        uint32_t bdst = sa(Bsm + (buf) * 128 * BSTR + r128 * BSTR + ch);       \
        cpa16(bdst, bsrc); cpa16(bdst + 16, bsrc + 8);                         \
    }

    GLOAD(0, 0);
    cp_commit();
    GLOAD(1, 1);
    cp_commit();
    cp_wait1();          // stage 0 resident (stage 1 may be in flight)
    __syncthreads();

    int stg = 0;
    for (int kt = 0; kt < EMB / 32; kt++) {
        if (kt + 2 < EMB / 32) {
            int nst = stg + 2; if (nst >= NSTG) nst -= NSTG;
            GLOAD(kt + 2, nst);
            cp_commit();
        }

        const __half* As = Asm + stg * 128 * ASTR;
        const __half* Bs = Bsm + stg * 128 * BSTR;
#pragma unroll
        for (int ks = 0; ks < 2; ks++) {
            int k0 = ks * 16;
            unsigned af[4][4], bf[4][2];
#pragma unroll
            for (int mt = 0; mt < 4; mt++) {
                uint32_t addr = sa(As + (wm + mt * 16 + ((lmat & 1) << 3) + lrow) * ASTR
                                   + k0 + ((lmat >> 1) << 3));
                LDSM4(af[mt][0], af[mt][1], af[mt][2], af[mt][3], addr);
            }
#pragma unroll
            for (int p = 0; p < 2; p++) {
                uint32_t addr = sa(Bs + (wn + p * 16 + ((lmat >> 1) << 3) + lrow) * BSTR
                                   + k0 + ((lmat & 1) << 3));
                LDSM4(bf[2*p][0], bf[2*p][1], bf[2*p+1][0], bf[2*p+1][1], addr);
            }
#pragma unroll
            for (int mt = 0; mt < 4; mt++)
#pragma unroll
                for (int nt = 0; nt < 4; nt++)
                    mma_f16(acc[mt][nt], af[mt], bf[nt]);
        }
        if (kt + 1 < EMB / 32) {
            if (kt + 2 < EMB / 32) cp_wait1();   // stage kt+1 resident
            else cp_wait0();                     // tail: only stage kt+1 left
            __syncthreads();
        }
        if (++stg == NSTG) stg = 0;
    }

    float os = ga.oscale[z];
#pragma unroll
    for (int mt = 0; mt < 4; mt++)
#pragma unroll
        for (int nt = 0; nt < 4; nt++) {
            int gm = bm + wm + mt * 16 + gid;
            int gn = bn + wn + nt * 8 + tig * 2;
            float b0 = bias[gn], b1 = bias[gn + 1];
            float v0 = (acc[mt][nt][0] + b0) * os;
            float v1 = (acc[mt][nt][1] + b1) * os;
            float v2 = (acc[mt][nt][2] + b0) * os;
            float v3 = (acc[mt][nt][3] + b1) * os;
            if (ga.half_out) {
                __half* C = (__half*)ga.out[z];
                *(__half2*)(C + (long)gm * EMB + gn) = __floats2half2_rn(v0, v1);
                *(__half2*)(C + (long)(gm + 8) * EMB + gn) = __floats2half2_rn(v2, v3);
            } else {
                float* C = (float*)ga.out[z];
                *(float2*)(C + (long)gm * EMB + gn) = make_float2(v0, v1);
                *(float2*)(C + (long)(gm + 8) * EMB + gn) = make_float2(v2, v3);
            }
        }
}

// ---------------- FP16 flash attention (unchanged from R10) -----------------
#define BQ 128
#define BKV 64
#define QSTR 72
#define KSTR 72
#define VSTR 72

__global__ __launch_bounds__(256, 2) void flash_f16(
    const __half* __restrict__ Q, const __half* __restrict__ K,
    const __half* __restrict__ Vt, const int* __restrict__ mask,
    const int* __restrict__ msum, __half* __restrict__ ctx)
{
    extern __shared__ __half fsm[];
    __half* Qs = fsm;
    __half* Ks = Qs + BQ * QSTR;
    __half* Vs = Ks + 2 * BKV * KSTR;

    int tid = threadIdx.x;
    int w = tid / 32, lane = tid % 32;
    int gid = lane >> 2, tig = lane & 3;
    int lrow = lane & 7, lmat = lane >> 3;
    int qt = blockIdx.x, h = blockIdx.y, b = blockIdx.z;
    int q0 = qt * BQ;
    int bh = b * NH + h;

    {
        int row = tid >> 1;
        int c0 = (tid & 1) * 32;
        const __half* g = Q + (long)(b * SEQ + q0 + row) * EMB + h * HD + c0;
        uint32_t s = sa(Qs + row * QSTR + c0);
#pragma unroll
        for (int j = 0; j < 4; j++) cpa16(s + j * 16, g + j * 8);
    }
    {
        int row = tid >> 2;
        int c0 = (tid & 3) * 16;
        const __half* kg = K + (long)(b * SEQ + row) * EMB + h * HD + c0;
        uint32_t ksm = sa(Ks + row * KSTR + c0);
        cpa16(ksm, kg); cpa16(ksm + 16, kg + 8);
        const __half* vg = Vt + ((long)bh * HD + row) * SEQ + c0;
        uint32_t vsm = sa(Vs + row * VSTR + c0);
        cpa16(vsm, vg); cpa16(vsm + 16, vg + 8);
    }
    cp_commit();
    cp_wait0();
    __syncthreads();

    unsigned aq[4][4];
#pragma unroll
    for (int ks = 0; ks < 4; ks++) {
        uint32_t addr = sa(Qs + (w * 16 + ((lmat & 1) << 3) + lrow) * QSTR
                           + ks * 16 + ((lmat >> 1) << 3));
        LDSM4(aq[ks][0], aq[ks][1], aq[ks][2], aq[ks][3], addr);
    }

    float o[8][4];
#pragma unroll
    for (int dt = 0; dt < 8; dt++)
#pragma unroll
        for (int r = 0; r < 4; r++) o[dt][r] = 0.0f;
    float mA = -1e30f, mB = -1e30f, lA = 0.0f, lB = 0.0f;

    for (int kt = 0; kt < NKT; kt++) {
        if (kt + 1 < NKT) {
            int nb = (kt + 1) & 1;
            int row = tid >> 2;
            int c0 = (tid & 3) * 16;
            const __half* kg = K + (long)(b * SEQ + (kt + 1) * BKV + row) * EMB + h * HD + c0;
            uint32_t ksm = sa(Ks + nb * BKV * KSTR + row * KSTR + c0);
            cpa16(ksm, kg); cpa16(ksm + 16, kg + 8);
            const __half* vg = Vt + ((long)bh * HD + row) * SEQ + (kt + 1) * BKV + c0;
            uint32_t vsm = sa(Vs + nb * HD * VSTR + row * VSTR + c0);
            cpa16(vsm, vg); cpa16(vsm + 16, vg + 8);
            cp_commit();
        }

        const __half* Kb = Ks + (kt & 1) * BKV * KSTR;
        const __half* Vb = Vs + (kt & 1) * HD * VSTR;

        float s[8][4];
#pragma unroll
        for (int nt = 0; nt < 8; nt++)
#pragma unroll
            for (int r = 0; r < 4; r++) s[nt][r] = 0.0f;
#pragma unroll
        for (int ks = 0; ks < 4; ks++) {
            int k0 = ks * 16;
            unsigned bk[8][2];
#pragma unroll
            for (int p = 0; p < 4; p++) {
                uint32_t addr = sa(Kb + (p * 16 + ((lmat >> 1) << 3) + lrow) * KSTR
                                   + k0 + ((lmat & 1) << 3));
                LDSM4(bk[2*p][0], bk[2*p][1], bk[2*p+1][0], bk[2*p+1][1], addr);
            }
#pragma unroll
            for (int nt = 0; nt < 8; nt++)
                mma_f16(s[nt], aq[ks], bk[nt]);
        }

        if (!msum[qt * NKT + kt]) {
            int qrA = q0 + w * 16 + gid;
            int qrB = qrA + 8;
#pragma unroll
            for (int nt = 0; nt < 8; nt++) {
                int kc = kt * 64 + nt * 8 + tig * 2;
                const int* mpA = mask + (long)qrA * SEQ + kc;
                const int* mpB = mask + (long)qrB * SEQ + kc;
                if (mpA[0] == 0) s[nt][0] = -1e30f;
                if (mpA[1] == 0) s[nt][1] = -1e30f;
                if (mpB[0] == 0) s[nt][2] = -1e30f;
                if (mpB[1] == 0) s[nt][3] = -1e30f;
            }
        }

        float mxA = -1e30f, mxB = -1e30f;
#pragma unroll
        for (int nt = 0; nt < 8; nt++) {
            mxA = fmaxf(mxA, fmaxf(s[nt][0], s[nt][1]));
            mxB = fmaxf(mxB, fmaxf(s[nt][2], s[nt][3]));
        }
#pragma unroll
        for (int off = 1; off < 4; off <<= 1) {
            mxA = fmaxf(mxA, __shfl_xor_sync(0xffffffffu, mxA, off));
            mxB = fmaxf(mxB, __shfl_xor_sync(0xffffffffu, mxB, off));
        }
        float mnA = fmaxf(mA, mxA), mnB = fmaxf(mB, mxB);
        float fA = __expf(mA - mnA), fB = __expf(mB - mnB);
        mA = mnA; mB = mnB;
        float sumA = 0.0f, sumB = 0.0f;
#pragma unroll
        for (int nt = 0; nt < 8; nt++) {
            s[nt][0] = __expf(s[nt][0] - mA);
            s[nt][1] = __expf(s[nt][1] - mA);
            s[nt][2] = __expf(s[nt][2] - mB);
            s[nt][3] = __expf(s[nt][3] - mB);
            sumA += s[nt][0] + s[nt][1];
            sumB += s[nt][2] + s[nt][3];
        }
#pragma unroll
        for (int off = 1; off < 4; off <<= 1) {
            sumA += __shfl_xor_sync(0xffffffffu, sumA, off);
            sumB += __shfl_xor_sync(0xffffffffu, sumB, off);
        }
        lA = lA * fA + sumA;
        lB = lB * fB + sumB;
#pragma unroll
        for (int dt = 0; dt < 8; dt++) {
            o[dt][0] *= fA; o[dt][1] *= fA;
            o[dt][2] *= fB; o[dt][3] *= fB;
        }

#pragma unroll
        for (int ks = 0; ks < 4; ks++) {
            unsigned pa[4];
            pa[0] = h2u(__floats2half2_rn(s[2*ks][0],   s[2*ks][1]));
            pa[1] = h2u(__floats2half2_rn(s[2*ks][2],   s[2*ks][3]));
            pa[2] = h2u(__floats2half2_rn(s[2*ks+1][0], s[2*ks+1][1]));
            pa[3] = h2u(__floats2half2_rn(s[2*ks+1][2], s[2*ks+1][3]));
            int k0 = ks * 16;
            unsigned bv[8][2];
#pragma unroll
            for (int p = 0; p < 4; p++) {
                uint32_t addr = sa(Vb + (p * 16 + ((lmat >> 1) << 3) + lrow) * VSTR
                                   + k0 + ((lmat & 1) << 3));
                LDSM4(bv[2*p][0], bv[2*p][1], bv[2*p+1][0], bv[2*p+1][1], addr);
            }
#pragma unroll
            for (int dt = 0; dt < 8; dt++)
                mma_f16(o[dt], pa, bv[dt]);
        }

        if (kt + 1 < NKT) {
            cp_wait0();
            __syncthreads();
        }
    }

    float invA = 1.0f / lA, invB = 1.0f / lB;
    long rowA = (long)(b * SEQ + q0 + w * 16 + gid) * EMB;
    long rowB = rowA + 8L * EMB;
#pragma unroll
    for (int dt = 0; dt < 8; dt++) {
        int gn = h * HD + dt * 8 + tig * 2;
        *(__half2*)(ctx + rowA + gn) = __floats2half2_rn(o[dt][0] * invA, o[dt][1] * invA);
        *(__half2*)(ctx + rowB + gn) = __floats2half2_rn(o[dt][2] * invB, o[dt][3] * invB);
    }
}

// ---------------- launch ----------------------------------------------------
extern "C" void kernel_launch(void* const* d_in, const int* in_sizes, int n_in,
                              void* d_out, int out_size)
{
    const float* x    = (const float*)d_in[0];
    const int*   mask = (const int*)  d_in[1];
    const float* Wq   = (const float*)d_in[2];
    const float* bq   = (const float*)d_in[3];
    const float* Wk   = (const float*)d_in[4];
    const float* bk   = (const float*)d_in[5];
    const float* Wv   = (const float*)d_in[6];
    const float* bv   = (const float*)d_in[7];
    const float* Wo   = (const float*)d_in[8];
    const float* bo   = (const float*)d_in[9];
    float* out = (float*)d_out;

    __half *pWq, *pWk, *pWv, *pWo, *pXr, *pQ, *pK, *pV, *pVt, *pCtx;
    int* pMsum;
    cudaGetSymbolAddress((void**)&pWq, g_Wq);
    cudaGetSymbolAddress((void**)&pWk, g_Wk);
    cudaGetSymbolAddress((void**)&pWv, g_Wv);
    cudaGetSymbolAddress((void**)&pWo, g_Wo);
    cudaGetSymbolAddress((void**)&pXr, g_xr);
    cudaGetSymbolAddress((void**)&pQ,  g_Q);
    cudaGetSymbolAddress((void**)&pK,  g_K);
    cudaGetSymbolAddress((void**)&pV,  g_V);
    cudaGetSymbolAddress((void**)&pVt, g_Vt);
    cudaGetSymbolAddress((void**)&pCtx, g_ctx);
    cudaGetSymbolAddress((void**)&pMsum, g_msum);

    const int gemm_smem  = (NSTG*128*ASTR + NSTG*128*BSTR) * (int)sizeof(__half);    // 60KB
    const int flash_smem = (BQ*QSTR + 2*BKV*KSTR + 2*HD*VSTR) * (int)sizeof(__half); // ~54KB
    cudaFuncSetAttribute(gemm_f16, cudaFuncAttributeMaxDynamicSharedMemorySize, gemm_smem);
    cudaFuncSetAttribute(flash_f16, cudaFuncAttributeMaxDynamicSharedMemorySize, flash_smem);

    // 1. prolog
    Exp4 e;
    e.W[0] = Wq; e.W[1] = Wk; e.W[2] = Wv; e.W[3] = Wo;
    e.Wb[0] = pWq; e.Wb[1] = pWk; e.Wb[2] = pWv; e.Wb[3] = pWo;
    expand4_kernel<<<dim3(NBQ*NBQ/256, 4), 256>>>(e);
    round_kernel<<<(NROWS*EMB/4 + 255)/256, 256>>>(x, pXr, NROWS*EMB/4);
    mask_summary<<<NQT*NKT, 256>>>(mask, pMsum);

    // 2. fused Q/K/V projections (Q prescaled by 1/8; all fp16 outputs)
    GemmArgs qkv;
    qkv.A = pXr;
    qkv.W[0] = pWq; qkv.W[1] = pWk; qkv.W[2] = pWv;
    qkv.bias[0] = bq; qkv.bias[1] = bk; qkv.bias[2] = bv;
    qkv.out[0] = pQ; qkv.out[1] = pK; qkv.out[2] = pV;
    qkv.oscale[0] = 0.125f; qkv.oscale[1] = 1.0f; qkv.oscale[2] = 1.0f;
    qkv.half_out = 1;
    dim3 ggrid(EMB/128, NROWS/128, 3);
    gemm_f16<<<ggrid, 256, gemm_smem>>>(qkv);

    // 2b. transpose V -> [b,h,d,s]
    vtrans_kernel<<<dim3(SEQ/64, NBATCH*NH), 256>>>(pV, pVt);

    // 3. attention
    dim3 agrid(SEQ/BQ, NH, NBATCH);
    flash_f16<<<agrid, 256, flash_smem>>>(pQ, pK, pVt, mask, pMsum, pCtx);

    // 4. output projection -> d_out (fp32)
    GemmArgs og;
    og.A = pCtx;
    og.W[0] = pWo; og.W[1] = pWo; og.W[2] = pWo;
    og.bias[0] = bo; og.bias[1] = bo; og.bias[2] = bo;
    og.out[0] = out; og.out[1] = out; og.out[2] = out;
    og.oscale[0] = 1.0f; og.oscale[1] = 1.0f; og.oscale[2] = 1.0f;
    og.half_out = 0;
    dim3 ogrid(EMB/128, NROWS/128, 1);
    gemm_f16<<<ogrid, 256, gemm_smem>>>(og);
}

// round 16
// speedup vs baseline: 1.0864x; 1.0559x over previous
#include <cuda_runtime.h>
#include <cuda_fp16.h>
#include <cstdint>
#include <math.h>

#define SEQ 2048
#define EMB 1024
#define NBQ 256
#define NH 16
#define HD 64
#define NBATCH 2
#define NROWS (NBATCH*SEQ)   // 4096
#define NKT (SEQ/64)         // 32 kv tiles
#define NQT (SEQ/128)        // 16 q tiles

// ---------------- scratch (device globals) ---------------------------------
__device__ __half g_Wq[EMB*EMB];     // transposed [out][in]
__device__ __half g_Wk[EMB*EMB];
__device__ __half g_Wv[EMB*EMB];
__device__ __half g_Wo[EMB*EMB];
__device__ __half g_xr[NROWS*EMB];   // fp16 input
__device__ __half g_Q[NROWS*EMB];    // prescaled by 1/8
__device__ __half g_K[NROWS*EMB];
__device__ __half g_V[NROWS*EMB];    // [b,s,h,d]
__device__ __half g_ctx[NROWS*EMB];
__device__ int    g_msum[NQT*NKT];

// ---------------- helpers ---------------------------------------------------
__device__ __forceinline__ uint32_t h2u(__half2 h) {
    return *reinterpret_cast<uint32_t*>(&h);
}

__device__ __forceinline__ void mma_f16(float* d, const unsigned* a, const unsigned* b) {
    asm volatile(
        "mma.sync.aligned.m16n8k16.row.col.f32.f16.f16.f32 "
        "{%0,%1,%2,%3},{%4,%5,%6,%7},{%8,%9},{%0,%1,%2,%3};"
        : "+f"(d[0]), "+f"(d[1]), "+f"(d[2]), "+f"(d[3])
        : "r"(a[0]), "r"(a[1]), "r"(a[2]), "r"(a[3]), "r"(b[0]), "r"(b[1]));
}

#define LDSM4(r0, r1, r2, r3, addr)                                            \
    asm volatile("ldmatrix.sync.aligned.m8n8.x4.shared.b16 {%0,%1,%2,%3}, [%4];" \
                 : "=r"(r0), "=r"(r1), "=r"(r2), "=r"(r3) : "r"(addr))

#define LDSM4T(r0, r1, r2, r3, addr)                                           \
    asm volatile("ldmatrix.sync.aligned.m8n8.x4.trans.shared.b16 {%0,%1,%2,%3}, [%4];" \
                 : "=r"(r0), "=r"(r1), "=r"(r2), "=r"(r3) : "r"(addr))

__device__ __forceinline__ uint32_t sa(const void* p) {
    return (uint32_t)__cvta_generic_to_shared(p);
}
__device__ __forceinline__ void cpa16(uint32_t s, const void* g) {
    asm volatile("cp.async.cg.shared.global [%0], [%1], 16;" :: "r"(s), "l"(g));
}
__device__ __forceinline__ void cp_commit() {
    asm volatile("cp.async.commit_group;" ::: "memory");
}
__device__ __forceinline__ void cp_wait0() {
    asm volatile("cp.async.wait_group 0;" ::: "memory");
}

// ---------------- x -> fp16 --------------------------------------------------
__global__ void round_kernel(const float* __restrict__ in, __half* __restrict__ outp, int n4) {
    int i = blockIdx.x * blockDim.x + threadIdx.x;
    if (i >= n4) return;
    float4 v = ((const float4*)in)[i];
    __half2* o = (__half2*)(outp + i * 4);
    o[0] = __floats2half2_rn(v.x, v.y);
    o[1] = __floats2half2_rn(v.z, v.w);
}

// ---------------- weight expansion: transposed [out][in], fp16 --------------
struct Exp4 { const float* W[4]; __half* Wb[4]; };

__global__ void expand4_kernel(Exp4 e) {
    int z = blockIdx.y;
    int idx = blockIdx.x * blockDim.x + threadIdx.x;
    if (idx >= NBQ * NBQ) return;
    int o = idx / NBQ;
    int n = idx % NBQ;
    const float* w = e.W[z] + (o * NBQ + n) * 4;
    float w0 = w[0], w1 = w[1], w2 = w[2], w3 = w[3];
    float M[4][4] = {{ w0,  w1,  w2,  w3},
                     {-w1,  w0,  w3, -w2},
                     {-w2, -w3,  w0,  w1},
                     {-w3,  w2, -w1,  w0}};
    __half* Wb = e.Wb[z];
#pragma unroll
    for (int k = 0; k < 4; k++) {
        __half2* row = (__half2*)(Wb + (long)(o * 4 + k) * EMB + n * 4);
        row[0] = __floats2half2_rn(M[0][k], M[1][k]);
        row[1] = __floats2half2_rn(M[2][k], M[3][k]);
    }
}

// ---------------- mask tile summary (128q x 64k tiles) ----------------------
__global__ void mask_summary(const int* __restrict__ mask, int* __restrict__ sum) {
    int tile = blockIdx.x;
    int qt = tile / NKT, kt = tile % NKT;
    int tid = threadIdx.x;
    int ok = 1;
    for (int i = tid; i < 128*16; i += 256) {
        int r = i / 16, c = i % 16;
        const int4* mp = (const int4*)(mask + (long)(qt*128 + r) * SEQ + kt*64) + c;
        int4 v = *mp;
        ok &= (v.x != 0) & (v.y != 0) & (v.z != 0) & (v.w != 0);
    }
    int allok = __syncthreads_and(ok);
    if (tid == 0) sum[tile] = allok;
}

// ---------------- FP16 GEMM (2-stage cp.async + ldmatrix, BK=32) ------------
// A: [M][K] half.  W: transposed [N][K] half.  (proven R10 form)
#define ASTR 40   // halves; 80B rows -> ldmatrix conflict-free
#define BSTR 40

struct GemmArgs {
    const __half* A;
    const __half* W[3];
    const float* bias[3];
    void* out[3];
    float oscale[3];
    int   half_out;
};

__global__ __launch_bounds__(256, 2) void gemm_f16(GemmArgs ga) {
    extern __shared__ __half gsm[];
    __half* Asm = gsm;                       // 2 * 128*ASTR
    __half* Bsm = gsm + 2 * 128 * ASTR;      // 2 * 128*BSTR

    int tid = threadIdx.x;
    int z = blockIdx.z;
    const __half* A = ga.A;
    const __half* W = ga.W[z];
    const float* bias = ga.bias[z];

    int bm = blockIdx.y * 128;
    int bn = blockIdx.x * 128;
    int warp = tid / 32, lane = tid % 32;
    int gid = lane >> 2, tig = lane & 3;
    int wm = (warp / 4) * 64, wn = (warp % 4) * 32;
    int lrow = lane & 7, lmat = lane >> 3;

    int r128 = tid >> 1;           // 0..127
    int ch   = (tid & 1) * 16;     // 16-half chunk (32B)

    float acc[4][4][4];
#pragma unroll
    for (int mt = 0; mt < 4; mt++)
#pragma unroll
        for (int nt = 0; nt < 4; nt++)
#pragma unroll
            for (int r = 0; r < 4; r++) acc[mt][nt][r] = 0.0f;

#define GLOAD(kt, buf)                                                         \
    {                                                                          \
        const __half* asrc = A + (long)(bm + r128) * EMB + (kt) * 32 + ch;     \
        uint32_t adst = sa(Asm + (buf) * 128 * ASTR + r128 * ASTR + ch);       \
        cpa16(adst, asrc); cpa16(adst + 16, asrc + 8);                         \
        const __half* bsrc = W + (long)(bn + r128) * EMB + (kt) * 32 + ch;     \
        uint32_t bdst = sa(Bsm + (buf) * 128 * BSTR + r128 * BSTR + ch);       \
        cpa16(bdst, bsrc); cpa16(bdst + 16, bsrc + 8);                         \
    }

    GLOAD(0, 0);
    cp_commit();
    cp_wait0();
    __syncthreads();

    for (int kt = 0; kt < EMB / 32; kt++) {
        if (kt + 1 < EMB / 32) {
            GLOAD(kt + 1, (kt + 1) & 1);
            cp_commit();
        }

        const __half* As = Asm + (kt & 1) * 128 * ASTR;
        const __half* Bs = Bsm + (kt & 1) * 128 * BSTR;
#pragma unroll
        for (int ks = 0; ks < 2; ks++) {
            int k0 = ks * 16;
            unsigned af[4][4], bf[4][2];
#pragma unroll
            for (int mt = 0; mt < 4; mt++) {
                uint32_t addr = sa(As + (wm + mt * 16 + ((lmat & 1) << 3) + lrow) * ASTR
                                   + k0 + ((lmat >> 1) << 3));
                LDSM4(af[mt][0], af[mt][1], af[mt][2], af[mt][3], addr);
            }
#pragma unroll
            for (int p = 0; p < 2; p++) {
                uint32_t addr = sa(Bs + (wn + p * 16 + ((lmat >> 1) << 3) + lrow) * BSTR
                                   + k0 + ((lmat & 1) << 3));
                LDSM4(bf[2*p][0], bf[2*p][1], bf[2*p+1][0], bf[2*p+1][1], addr);
            }
#pragma unroll
            for (int mt = 0; mt < 4; mt++)
#pragma unroll
                for (int nt = 0; nt < 4; nt++)
                    mma_f16(acc[mt][nt], af[mt], bf[nt]);
        }
        if (kt + 1 < EMB / 32) {
            cp_wait0();
            __syncthreads();
        }
    }

    float os = ga.oscale[z];
#pragma unroll
    for (int mt = 0; mt < 4; mt++)
#pragma unroll
        for (int nt = 0; nt < 4; nt++) {
            int gm = bm + wm + mt * 16 + gid;
            int gn = bn + wn + nt * 8 + tig * 2;
            float b0 = bias[gn], b1 = bias[gn + 1];
            float v0 = (acc[mt][nt][0] + b0) * os;
            float v1 = (acc[mt][nt][1] + b1) * os;
            float v2 = (acc[mt][nt][2] + b0) * os;
            float v3 = (acc[mt][nt][3] + b1) * os;
            if (ga.half_out) {
                __half* C = (__half*)ga.out[z];
                *(__half2*)(C + (long)gm * EMB + gn) = __floats2half2_rn(v0, v1);
                *(__half2*)(C + (long)(gm + 8) * EMB + gn) = __floats2half2_rn(v2, v3);
            } else {
                float* C = (float*)ga.out[z];
                *(float2*)(C + (long)gm * EMB + gn) = make_float2(v0, v1);
                *(float2*)(C + (long)(gm + 8) * EMB + gn) = make_float2(v2, v3);
            }
        }
}

// ---------------- FP16 flash attention (V via ldmatrix.trans) ---------------
#define BQ 128
#define BKV 64
#define QSTR 72
#define KSTR 72
#define VSTR 72

__global__ __launch_bounds__(256, 2) void flash_f16(
    const __half* __restrict__ Q, const __half* __restrict__ K,
    const __half* __restrict__ V, const int* __restrict__ mask,
    const int* __restrict__ msum, __half* __restrict__ ctx)
{
    extern __shared__ __half fsm[];
    __half* Qs = fsm;
    __half* Ks = Qs + BQ * QSTR;              // 2*BKV*KSTR (rows = s)
    __half* Vs = Ks + 2 * BKV * KSTR;         // 2*BKV*VSTR (rows = s, same as K)

    int tid = threadIdx.x;
    int w = tid / 32, lane = tid % 32;
    int gid = lane >> 2, tig = lane & 3;
    int lrow = lane & 7, lmat = lane >> 3;
    int qt = blockIdx.x, h = blockIdx.y, b = blockIdx.z;
    int q0 = qt * BQ;

    // Q tile
    {
        int row = tid >> 1;
        int c0 = (tid & 1) * 32;
        const __half* g = Q + (long)(b * SEQ + q0 + row) * EMB + h * HD + c0;
        uint32_t s = sa(Qs + row * QSTR + c0);
#pragma unroll
        for (int j = 0; j < 4; j++) cpa16(s + j * 16, g + j * 8);
    }
    // K / V tile 0 (both s-major [s][d], identical producer pattern)
    {
        int row = tid >> 2;
        int c0 = (tid & 3) * 16;
        long gr = (long)(b * SEQ + row) * EMB + h * HD + c0;
        uint32_t ksm = sa(Ks + row * KSTR + c0);
        cpa16(ksm, K + gr); cpa16(ksm + 16, K + gr + 8);
        uint32_t vsm = sa(Vs + row * VSTR + c0);
        cpa16(vsm, V + gr); cpa16(vsm + 16, V + gr + 8);
    }
    cp_commit();
    cp_wait0();
    __syncthreads();

    // hoist Q fragments
    unsigned aq[4][4];
#pragma unroll
    for (int ks = 0; ks < 4; ks++) {
        uint32_t addr = sa(Qs + (w * 16 + ((lmat & 1) << 3) + lrow) * QSTR
                           + ks * 16 + ((lmat >> 1) << 3));
        LDSM4(aq[ks][0], aq[ks][1], aq[ks][2], aq[ks][3], addr);
    }

    float o[8][4];
#pragma unroll
    for (int dt = 0; dt < 8; dt++)
#pragma unroll
        for (int r = 0; r < 4; r++) o[dt][r] = 0.0f;
    float mA = -1e30f, mB = -1e30f, lA = 0.0f, lB = 0.0f;

    for (int kt = 0; kt < NKT; kt++) {
        if (kt + 1 < NKT) {
            int nb = (kt + 1) & 1;
            int row = tid >> 2;
            int c0 = (tid & 3) * 16;
            long gr = (long)(b * SEQ + (kt + 1) * BKV + row) * EMB + h * HD + c0;
            uint32_t ksm = sa(Ks + nb * BKV * KSTR + row * KSTR + c0);
            cpa16(ksm, K + gr); cpa16(ksm + 16, K + gr + 8);
            uint32_t vsm = sa(Vs + nb * BKV * VSTR + row * VSTR + c0);
            cpa16(vsm, V + gr); cpa16(vsm + 16, V + gr + 8);
            cp_commit();
        }

        const __half* Kb = Ks + (kt & 1) * BKV * KSTR;
        const __half* Vb = Vs + (kt & 1) * BKV * VSTR;

        // S = Q K^T
        float s[8][4];
#pragma unroll
        for (int nt = 0; nt < 8; nt++)
#pragma unroll
            for (int r = 0; r < 4; r++) s[nt][r] = 0.0f;
#pragma unroll
        for (int ks = 0; ks < 4; ks++) {
            int k0 = ks * 16;
            unsigned bk[8][2];
#pragma unroll
            for (int p = 0; p < 4; p++) {
                uint32_t addr = sa(Kb + (p * 16 + ((lmat >> 1) << 3) + lrow) * KSTR
                                   + k0 + ((lmat & 1) << 3));
                LDSM4(bk[2*p][0], bk[2*p][1], bk[2*p+1][0], bk[2*p+1][1], addr);
            }
#pragma unroll
            for (int nt = 0; nt < 8; nt++)
                mma_f16(s[nt], aq[ks], bk[nt]);
        }

        // mask (only when tile contains zeros)
        if (!msum[qt * NKT + kt]) {
            int qrA = q0 + w * 16 + gid;
            int qrB = qrA + 8;
#pragma unroll
            for (int nt = 0; nt < 8; nt++) {
                int kc = kt * 64 + nt * 8 + tig * 2;
                const int* mpA = mask + (long)qrA * SEQ + kc;
                const int* mpB = mask + (long)qrB * SEQ + kc;
                if (mpA[0] == 0) s[nt][0] = -1e30f;
                if (mpA[1] == 0) s[nt][1] = -1e30f;
                if (mpB[0] == 0) s[nt][2] = -1e30f;
                if (mpB[1] == 0) s[nt][3] = -1e30f;
            }
        }

        // online softmax (rows gid / gid+8)
        float mxA = -1e30f, mxB = -1e30f;
#pragma unroll
        for (int nt = 0; nt < 8; nt++) {
            mxA = fmaxf(mxA, fmaxf(s[nt][0], s[nt][1]));
            mxB = fmaxf(mxB, fmaxf(s[nt][2], s[nt][3]));
        }
#pragma unroll
        for (int off = 1; off < 4; off <<= 1) {
            mxA = fmaxf(mxA, __shfl_xor_sync(0xffffffffu, mxA, off));
            mxB = fmaxf(mxB, __shfl_xor_sync(0xffffffffu, mxB, off));
        }
        float mnA = fmaxf(mA, mxA), mnB = fmaxf(mB, mxB);
        float fA = __expf(mA - mnA), fB = __expf(mB - mnB);
        mA = mnA; mB = mnB;
        float sumA = 0.0f, sumB = 0.0f;
#pragma unroll
        for (int nt = 0; nt < 8; nt++) {
            s[nt][0] = __expf(s[nt][0] - mA);
            s[nt][1] = __expf(s[nt][1] - mA);
            s[nt][2] = __expf(s[nt][2] - mB);
            s[nt][3] = __expf(s[nt][3] - mB);
            sumA += s[nt][0] + s[nt][1];
            sumB += s[nt][2] + s[nt][3];
        }
#pragma unroll
        for (int off = 1; off < 4; off <<= 1) {
            sumA += __shfl_xor_sync(0xffffffffu, sumA, off);
            sumB += __shfl_xor_sync(0xffffffffu, sumB, off);
        }
        lA = lA * fA + sumA;
        lB = lB * fB + sumB;
#pragma unroll
        for (int dt = 0; dt < 8; dt++) {
            o[dt][0] *= fA; o[dt][1] *= fA;
            o[dt][2] *= fB; o[dt][3] *= fB;
        }

        // O += P V : P packed from S-accum; V^T frags via ldmatrix.trans
        // trans source: rows = s (k-dim), cols = d (n-dim); matrix (k8, d8)
        // lmat&1 selects k-half, lmat>>1 selects d8-subgroup -> r0..r3 map to
        // bv[2p][0], bv[2p][1], bv[2p+1][0], bv[2p+1][1].
#pragma unroll
        for (int ks = 0; ks < 4; ks++) {
            unsigned pa[4];
            pa[0] = h2u(__floats2half2_rn(s[2*ks][0],   s[2*ks][1]));
            pa[1] = h2u(__floats2half2_rn(s[2*ks][2],   s[2*ks][3]));
            pa[2] = h2u(__floats2half2_rn(s[2*ks+1][0], s[2*ks+1][1]));
            pa[3] = h2u(__floats2half2_rn(s[2*ks+1][2], s[2*ks+1][3]));
            int k0 = ks * 16;
            unsigned bv[8][2];
#pragma unroll
            for (int p = 0; p < 4; p++) {
                uint32_t addr = sa(Vb + (k0 + ((lmat & 1) << 3) + lrow) * VSTR
                                   + p * 16 + ((lmat >> 1) << 3));
                LDSM4T(bv[2*p][0], bv[2*p][1], bv[2*p+1][0], bv[2*p+1][1], addr);
            }
#pragma unroll
            for (int dt = 0; dt < 8; dt++)
                mma_f16(o[dt], pa, bv[dt]);
        }

        if (kt + 1 < NKT) {
            cp_wait0();
            __syncthreads();
        }
    }

    // finalize -> ctx fp16
    float invA = 1.0f / lA, invB = 1.0f / lB;
    long rowA = (long)(b * SEQ + q0 + w * 16 + gid) * EMB;
    long rowB = rowA + 8L * EMB;
#pragma unroll
    for (int dt = 0; dt < 8; dt++) {
        int gn = h * HD + dt * 8 + tig * 2;
        *(__half2*)(ctx + rowA + gn) = __floats2half2_rn(o[dt][0] * invA, o[dt][1] * invA);
        *(__half2*)(ctx + rowB + gn) = __floats2half2_rn(o[dt][2] * invB, o[dt][3] * invB);
    }
}

// ---------------- launch ----------------------------------------------------
extern "C" void kernel_launch(void* const* d_in, const int* in_sizes, int n_in,
                              void* d_out, int out_size)
{
    const float* x    = (const float*)d_in[0];
    const int*   mask = (const int*)  d_in[1];
    const float* Wq   = (const float*)d_in[2];
    const float* bq   = (const float*)d_in[3];
    const float* Wk   = (const float*)d_in[4];
    const float* bk   = (const float*)d_in[5];
    const float* Wv   = (const float*)d_in[6];
    const float* bv   = (const float*)d_in[7];
    const float* Wo   = (const float*)d_in[8];
    const float* bo   = (const float*)d_in[9];
    float* out = (float*)d_out;

    __half *pWq, *pWk, *pWv, *pWo, *pXr, *pQ, *pK, *pV, *pCtx;
    int* pMsum;
    cudaGetSymbolAddress((void**)&pWq, g_Wq);
    cudaGetSymbolAddress((void**)&pWk, g_Wk);
    cudaGetSymbolAddress((void**)&pWv, g_Wv);
    cudaGetSymbolAddress((void**)&pWo, g_Wo);
    cudaGetSymbolAddress((void**)&pXr, g_xr);
    cudaGetSymbolAddress((void**)&pQ,  g_Q);
    cudaGetSymbolAddress((void**)&pK,  g_K);
    cudaGetSymbolAddress((void**)&pV,  g_V);
    cudaGetSymbolAddress((void**)&pCtx, g_ctx);
    cudaGetSymbolAddress((void**)&pMsum, g_msum);

    const int gemm_smem  = (2*128*ASTR + 2*128*BSTR) * (int)sizeof(__half);            // 40KB
    const int flash_smem = (BQ*QSTR + 2*BKV*KSTR + 2*BKV*VSTR) * (int)sizeof(__half);  // ~54KB
    cudaFuncSetAttribute(gemm_f16, cudaFuncAttributeMaxDynamicSharedMemorySize, gemm_smem);
    cudaFuncSetAttribute(flash_f16, cudaFuncAttributeMaxDynamicSharedMemorySize, flash_smem);

    // 1. prolog
    Exp4 e;
    e.W[0] = Wq; e.W[1] = Wk; e.W[2] = Wv; e.W[3] = Wo;
    e.Wb[0] = pWq; e.Wb[1] = pWk; e.Wb[2] = pWv; e.Wb[3] = pWo;
    expand4_kernel<<<dim3(NBQ*NBQ/256, 4), 256>>>(e);
    round_kernel<<<(NROWS*EMB/4 + 255)/256, 256>>>(x, pXr, NROWS*EMB/4);
    mask_summary<<<NQT*NKT, 256>>>(mask, pMsum);

    // 2. fused Q/K/V projections (Q prescaled by 1/8; all fp16 outputs)
    GemmArgs qkv;
    qkv.A = pXr;
    qkv.W[0] = pWq; qkv.W[1] = pWk; qkv.W[2] = pWv;
    qkv.bias[0] = bq; qkv.bias[1] = bk; qkv.bias[2] = bv;
    qkv.out[0] = pQ; qkv.out[1] = pK; qkv.out[2] = pV;
    qkv.oscale[0] = 0.125f; qkv.oscale[1] = 1.0f; qkv.oscale[2] = 1.0f;
    qkv.half_out = 1;
    dim3 ggrid(EMB/128, NROWS/128, 3);
    gemm_f16<<<ggrid, 256, gemm_smem>>>(qkv);

    // 3. attention (V consumed directly; transpose folded into ldmatrix.trans)
    dim3 agrid(SEQ/BQ, NH, NBATCH);
    flash_f16<<<agrid, 256, flash_smem>>>(pQ, pK, pV, mask, pMsum, pCtx);

    // 4. output projection -> d_out (fp32)
    GemmArgs og;
    og.A = pCtx;
    og.W[0] = pWo; og.W[1] = pWo; og.W[2] = pWo;
    og.bias[0] = bo; og.bias[1] = bo; og.bias[2] = bo;
    og.out[0] = out; og.out[1] = out; og.out[2] = out;
    og.oscale[0] = 1.0f; og.oscale[1] = 1.0f; og.oscale[2] = 1.0f;
    og.half_out = 0;
    dim3 ogrid(EMB/128, NROWS/128, 1);
    gemm_f16<<<ogrid, 256, gemm_smem>>>(og);
}